// round 12
// baseline (speedup 1.0000x reference)
#include <cuda_runtime.h>
#include <cuda_fp16.h>
#include <cstdint>

#define D_FEAT      64
#define N_NODES_MAX 100000
#define EPS         64            // edges per 16-thread group (R9-proven)
#define SUBS        8             // groups per block
#define EPB         (EPS * SUBS)  // 512 edges per block
#define PAD         4             // prefetch overrun pad
#define THREADS     128

// Scratch (allocation-free). Intermediate hop in fp16.
__device__ __half g_tmp[(size_t)N_NODES_MAX * D_FEAT];

__device__ __forceinline__ void red_add_v4(float* p, float4 a) {
    asm volatile("red.global.add.v4.f32 [%0], {%1, %2, %3, %4};"
                 :: "l"(p), "f"(a.x), "f"(a.y), "f"(a.z), "f"(a.w)
                 : "memory");
}
__device__ __forceinline__ void red_add_h2(uint32_t* p, float2 v) {
    __half2 h = __float22half2_rn(v);
    asm volatile("red.global.add.noftz.f16x2 [%0], %1;"
                 :: "l"(p), "r"(*reinterpret_cast<uint32_t*>(&h))
                 : "memory");
}

// ---- per-dtype feature row helpers (each d4-thread owns 4 features) ----
template <bool HALF>
__device__ __forceinline__ float4 ld_feat(const char* p) {
    if (HALF) {
        uint2 r = *reinterpret_cast<const uint2*>(p);
        float2 a = __half22float2(*reinterpret_cast<__half2*>(&r.x));
        float2 b = __half22float2(*reinterpret_cast<__half2*>(&r.y));
        return make_float4(a.x, a.y, b.x, b.y);
    } else {
        return *reinterpret_cast<const float4*>(p);
    }
}
template <bool HALF>
__device__ __forceinline__ void st_feat(char* p, float4 v) {
    if (HALF) {
        uint2 u;
        __half2 h0 = __float22half2_rn(make_float2(v.x, v.y));
        __half2 h1 = __float22half2_rn(make_float2(v.z, v.w));
        u.x = *reinterpret_cast<uint32_t*>(&h0);
        u.y = *reinterpret_cast<uint32_t*>(&h1);
        *reinterpret_cast<uint2*>(p) = u;
    } else {
        *reinterpret_cast<float4*>(p) = v;
    }
}
template <bool HALF>
__device__ __forceinline__ void red_feat(char* p, float4 v) {
    if (HALF) {
        uint32_t* u = reinterpret_cast<uint32_t*>(p);
        red_add_h2(u + 0, make_float2(v.x, v.y));
        red_add_h2(u + 1, make_float2(v.z, v.w));
    } else {
        red_add_v4(reinterpret_cast<float*>(p), v);
    }
}

// Sorted-row SpMM (16-thread groups, 2/warp), software-pipelined: batch k+1's
// metadata + gathers are issued BEFORE batch k is consumed, so loads are in
// flight across the whole consume phase. Interior runs -> exclusive STG,
// boundary runs -> red.add into pre-zeroed dst.
template <bool SRC_H, bool DST_H>
__global__ void __launch_bounds__(THREADS)
spmm_kernel(const char* __restrict__ src,
            const int*  __restrict__ erow,
            const int*  __restrict__ ecol,
            const float* __restrict__ eval,
            char*       __restrict__ dst,
            int n_edges) {
    constexpr int SRC_RB = SRC_H ? 128 : 256;
    constexpr int DST_RB = DST_H ? 128 : 256;
    constexpr int SRC_TB = SRC_H ? 8 : 16;
    constexpr int DST_TB = DST_H ? 8 : 16;

    __shared__ alignas(16) int   s_row[EPB + PAD];
    __shared__ alignas(16) int   s_off[EPB + PAD];   // col * SRC_RB
    __shared__ alignas(16) float s_val[EPB + PAD];

    const int base = blockIdx.x * EPB;
    const int tid  = threadIdx.x;

    // Vectorized staging; pad with last valid row, val = 0.
    {
        const int i = tid * 4;
        const int e = base + i;
        if (e + 3 < n_edges) {
            int4   r = *reinterpret_cast<const int4*>(erow + e);
            int4   c = *reinterpret_cast<const int4*>(ecol + e);
            float4 v = *reinterpret_cast<const float4*>(eval + e);
            c.x *= SRC_RB; c.y *= SRC_RB; c.z *= SRC_RB; c.w *= SRC_RB;
            *reinterpret_cast<int4*>(s_row + i)   = r;
            *reinterpret_cast<int4*>(s_off + i)   = c;
            *reinterpret_cast<float4*>(s_val + i) = v;
        } else {
            #pragma unroll
            for (int k = 0; k < 4; k++) {
                int ee   = e + k;
                int esrc = min(ee, n_edges - 1);
                int in   = (ee < n_edges);
                s_row[i + k] = erow[esrc];
                s_off[i + k] = in ? ecol[esrc] * SRC_RB : 0;
                s_val[i + k] = in ? eval[esrc] : 0.f;
            }
        }
        if (tid < PAD) {                         // prefetch-overrun pad
            int ee   = base + EPB + tid;
            int esrc = min(ee, n_edges - 1);
            int in   = (ee < n_edges);
            s_row[EPB + tid] = erow[esrc];
            s_off[EPB + tid] = in ? ecol[esrc] * SRC_RB : 0;
            s_val[EPB + tid] = in ? eval[esrc] : 0.f;
        }
    }
    __syncthreads();

    const int d4  = tid & 15;
    const int sub = tid >> 4;
    const int off = sub * EPS;
    const char* sp = src + d4 * SRC_TB;
    char*       dp = dst + d4 * DST_TB;

    int    cur       = s_row[off];
    int    run_start = 0;
    float4 acc       = make_float4(0.f, 0.f, 0.f, 0.f);

    // Pipeline prologue: load batch 0.
    int4   r4 = *reinterpret_cast<const int4*>(s_row + off);
    int4   c4 = *reinterpret_cast<const int4*>(s_off + off);
    float4 v4 = *reinterpret_cast<const float4*>(s_val + off);
    float4 g0 = ld_feat<SRC_H>(sp + c4.x);
    float4 g1 = ld_feat<SRC_H>(sp + c4.y);
    float4 g2 = ld_feat<SRC_H>(sp + c4.z);
    float4 g3 = ld_feat<SRC_H>(sp + c4.w);

    #pragma unroll
    for (int ib = 0; ib < EPS; ib += 4) {
        // Prefetch batch k+1 (pad guarantees validity; last prefetch unused).
        const int4   r4n = *reinterpret_cast<const int4*>(s_row + off + ib + 4);
        const int4   c4n = *reinterpret_cast<const int4*>(s_off + off + ib + 4);
        const float4 v4n = *reinterpret_cast<const float4*>(s_val + off + ib + 4);
        const float4 n0 = ld_feat<SRC_H>(sp + c4n.x);
        const float4 n1 = ld_feat<SRC_H>(sp + c4n.y);
        const float4 n2 = ld_feat<SRC_H>(sp + c4n.z);
        const float4 n3 = ld_feat<SRC_H>(sp + c4n.w);

        #define STEP(R, V, G, IDX)                                           \
        do {                                                                 \
            if ((R) != cur) {                                                \
                char* p = dp + (size_t)cur * DST_RB;                         \
                if (run_start > 0) {                                         \
                    st_feat<DST_H>(p, acc);       /* exclusive interior */   \
                } else {                                                     \
                    red_feat<DST_H>(p, acc);      /* boundary */             \
                }                                                            \
                acc = make_float4(0.f, 0.f, 0.f, 0.f);                       \
                cur = (R);                                                   \
                run_start = (IDX);                                           \
            }                                                                \
            acc.x += (V) * (G).x;                                            \
            acc.y += (V) * (G).y;                                            \
            acc.z += (V) * (G).z;                                            \
            acc.w += (V) * (G).w;                                            \
        } while (0)

        // Consume batch k (its loads have been in flight one full iteration).
        STEP(r4.x, v4.x, g0, ib + 0);
        STEP(r4.y, v4.y, g1, ib + 1);
        STEP(r4.z, v4.z, g2, ib + 2);
        STEP(r4.w, v4.w, g3, ib + 3);
        #undef STEP

        // Rotate (register renames after unroll).
        r4 = r4n; v4 = v4n;
        g0 = n0; g1 = n1; g2 = n2; g3 = n3;
    }

    // Final run may continue into the next group -> always atomic.
    red_feat<DST_H>(dp + (size_t)cur * DST_RB, acc);
}

extern "C" void kernel_launch(void* const* d_in, const int* in_sizes, int n_in,
                              void* d_out, int out_size) {
    const char*  x    = (const char*) d_in[0];
    const int*   erow = (const int*)  d_in[1];
    const int*   ecol = (const int*)  d_in[2];
    const float* eval = (const float*)d_in[3];
    char*        out  = (char*)d_out;

    const int n_edges = in_sizes[1];
    const int n_rows  = out_size / D_FEAT;
    const int n_elems = n_rows * D_FEAT;

    void* tmp_sym = nullptr;
    cudaGetSymbolAddress(&tmp_sym, g_tmp);
    char* tmp = (char*)tmp_sym;

    const int sgrid = (n_edges + EPB - 1) / EPB;

    // Host-side resources for the fork/join (no device memory involved).
    static cudaStream_t side = nullptr;
    static cudaEvent_t  ev_fork = nullptr, ev_join = nullptr;
    if (!side) {
        cudaStreamCreateWithFlags(&side, cudaStreamNonBlocking);
        cudaEventCreateWithFlags(&ev_fork, cudaEventDisableTiming);
        cudaEventCreateWithFlags(&ev_join, cudaEventDisableTiming);
    }

    // Critical path: zero tmp (needed by hop 1's boundary red.adds).
    cudaMemsetAsync(tmp, 0, (size_t)n_elems * 2);

    // Fork: zero out on the side stream, overlapping hop 1.
    cudaEventRecord(ev_fork, 0);
    cudaStreamWaitEvent(side, ev_fork, 0);
    cudaMemsetAsync(out, 0, (size_t)n_elems * 4, side);
    cudaEventRecord(ev_join, side);

    // Hop 1: tmp(fp16) = A @ x(fp32)   (overlaps memset(out))
    spmm_kernel<false, true><<<sgrid, THREADS>>>(x, erow, ecol, eval, tmp, n_edges);

    // Join: out must be zeroed before hop 2's red.adds.
    cudaStreamWaitEvent(0, ev_join, 0);

    // Hop 2: out(fp32) = A @ tmp(fp16)
    spmm_kernel<true, false><<<sgrid, THREADS>>>(tmp, erow, ecol, eval, out, n_edges);
}